// round 12
// baseline (speedup 1.0000x reference)
#include <cuda_runtime.h>
#include <cuda_bf16.h>
#include <math_constants.h>

// out = x * (1 + sigmoid(max_{h,w} x))  per (b,c) plane.
// x: (32, 512, 56, 56) fp32. One CTA per plane (3136 floats = 784 float4).
// Each thread holds its slice in registers across the block max-reduce, so x
// is read from HBM exactly once and written exactly once (411 MB total).

#define HW4 784        // 56*56/4 float4 per plane
#define THREADS 256

__global__ __launch_bounds__(THREADS)
void dca_fused_kernel(const float* __restrict__ x, float* __restrict__ out) {
    const long long base = (long long)blockIdx.x * (HW4 * 4);
    const float4* __restrict__ xin  = reinterpret_cast<const float4*>(x + base);
    float4*       __restrict__ xout = reinterpret_cast<float4*>(out + base);

    const int tid  = threadIdx.x;
    const int lane = tid & 31;
    const int wid  = tid >> 5;

    // Load plane slice into registers (3 float4 each; 16 threads take a 4th).
    float4 v0 = xin[tid];
    float4 v1 = xin[tid + 256];
    float4 v2 = xin[tid + 512];
    const bool has4 = (tid < HW4 - 768);   // tid < 16
    float4 v3;
    if (has4) v3 = xin[tid + 768];

    float m = fmaxf(fmaxf(v0.x, v0.y), fmaxf(v0.z, v0.w));
    m = fmaxf(m, fmaxf(fmaxf(v1.x, v1.y), fmaxf(v1.z, v1.w)));
    m = fmaxf(m, fmaxf(fmaxf(v2.x, v2.y), fmaxf(v2.z, v2.w)));
    if (has4)
        m = fmaxf(m, fmaxf(fmaxf(v3.x, v3.y), fmaxf(v3.z, v3.w)));

    // Warp max-reduce.
    #pragma unroll
    for (int o = 16; o > 0; o >>= 1)
        m = fmaxf(m, __shfl_xor_sync(0xffffffffu, m, o));

    __shared__ float wmax[8];
    __shared__ float scale_s;
    if (lane == 0) wmax[wid] = m;
    __syncthreads();

    if (wid == 0) {
        float t = (lane < 8) ? wmax[lane] : -CUDART_INF_F;
        #pragma unroll
        for (int o = 4; o > 0; o >>= 1)
            t = fmaxf(t, __shfl_xor_sync(0xffffffffu, t, o));
        if (lane == 0) {
            // gate = sigmoid(t); multiplier = 1 + gate
            float g = 1.0f / (1.0f + __expf(-t));
            scale_s = 1.0f + g;
        }
    }
    __syncthreads();

    const float s = scale_s;

    v0.x *= s; v0.y *= s; v0.z *= s; v0.w *= s;
    v1.x *= s; v1.y *= s; v1.z *= s; v1.w *= s;
    v2.x *= s; v2.y *= s; v2.z *= s; v2.w *= s;

    xout[tid]       = v0;
    xout[tid + 256] = v1;
    xout[tid + 512] = v2;
    if (has4) {
        v3.x *= s; v3.y *= s; v3.z *= s; v3.w *= s;
        xout[tid + 768] = v3;
    }
}

extern "C" void kernel_launch(void* const* d_in, const int* in_sizes, int n_in,
                              void* d_out, int out_size) {
    const float* x = (const float*)d_in[0];
    float* out = (float*)d_out;
    // planes = B * C = total / (56*56)
    const int planes = in_sizes[0] / (HW4 * 4);   // 16384
    dca_fused_kernel<<<planes, THREADS>>>(x, out);
}